// round 2
// baseline (speedup 1.0000x reference)
#include <cuda_runtime.h>
#include <cuda_bf16.h>
#include <math.h>

// Shapes
#define Bz 64
#define Hh 1024
#define Vv 32000
#define Ss 512
#define Ee 2048   // 2H
#define H3 3072   // 3H
#define H4 4096   // 4H

// ---------------- scratch ----------------
__device__ __align__(16) float g_x[Bz * Hh];            // embedded input
__device__ __align__(16) float g_part[8 * Bz * H4];     // split-K partials (worst case 8 x 64 x 4096)
__device__ __align__(16) float g_gates[Bz * H4];
__device__ __align__(16) float g_q[Bz * Ee];
__device__ __align__(16) float g_scores[Bz * Ss];
__device__ __align__(16) float g_aw[Bz * Ss];
__device__ __align__(16) float g_cin[Bz * H3];          // [h_new | context]
__device__ __align__(16) float g_cc[Bz * H3];           // tanh(concat)

// ---------------- generic M=64 GEMM ----------------
// C[64,N] = A[64,K-range] * W
// BLAYOUT 0: W is [N,K] row-major (use W[n*K+k])  -> "x @ W.T"
// BLAYOUT 1: W is [K,N] row-major (use W[k*N+n])  -> "x @ W"
// grid.x = N/64 tiles, grid.y = split-K slice. Each slice covers kChunks*64 of K.
// WRITE_PART: write raw partial to parts[(sliceOff+by)*64*N + ...]
// else (grid.y==1): write C directly with optional bias.
#define SWZ(k) ((((k) >> 2) & 15) << 2)

template<int BLAYOUT, bool WRITE_PART>
__global__ void __launch_bounds__(256) gemm_m64(
    const float* __restrict__ A, const float* __restrict__ W,
    float* __restrict__ dst, const float* __restrict__ bias,
    int N, int K, int kChunks, int sliceOff)
{
    __shared__ __align__(16) float As[64][65];   // m-major, padded
    __shared__ __align__(16) float Bs[64][64];   // k-major, XOR swizzled

    const int tid = threadIdx.x;
    const int tx = tid & 15;       // column group
    const int ty = tid >> 4;       // row group
    const int n0 = blockIdx.x * 64;
    const int kBase = blockIdx.y * kChunks * 64;

    float acc[4][4] = {};

    for (int c = 0; c < kChunks; ++c) {
        const int k0 = kBase + c * 64;
        // load A tile (coalesced along k)
        #pragma unroll
        for (int it = 0; it < 4; ++it) {
            int lin = tid + it * 256;
            int m = lin >> 4, k4 = lin & 15;
            float4 v = *(const float4*)&A[(size_t)m * K + k0 + k4 * 4];
            As[m][k4 * 4 + 0] = v.x; As[m][k4 * 4 + 1] = v.y;
            As[m][k4 * 4 + 2] = v.z; As[m][k4 * 4 + 3] = v.w;
        }
        // load W tile
        if (BLAYOUT == 0) {
            #pragma unroll
            for (int it = 0; it < 4; ++it) {
                int lin = tid + it * 256;
                int n = lin >> 4, k4 = lin & 15;
                float4 v = *(const float4*)&W[(size_t)(n0 + n) * K + k0 + k4 * 4];
                int k = k4 * 4;
                Bs[k + 0][n ^ SWZ(k + 0)] = v.x;
                Bs[k + 1][n ^ SWZ(k + 1)] = v.y;
                Bs[k + 2][n ^ SWZ(k + 2)] = v.z;
                Bs[k + 3][n ^ SWZ(k + 3)] = v.w;
            }
        } else {
            #pragma unroll
            for (int it = 0; it < 4; ++it) {
                int lin = tid + it * 256;
                int k = lin >> 4, n4 = lin & 15;
                float4 v = *(const float4*)&W[(size_t)(k0 + k) * N + n0 + n4 * 4];
                *(float4*)&Bs[k][(n4 * 4) ^ SWZ(k)] = v;
            }
        }
        __syncthreads();
        #pragma unroll 16
        for (int k = 0; k < 64; ++k) {
            float a0 = As[ty * 4 + 0][k];
            float a1 = As[ty * 4 + 1][k];
            float a2 = As[ty * 4 + 2][k];
            float a3 = As[ty * 4 + 3][k];
            float4 bv = *(const float4*)&Bs[k][(tx * 4) ^ SWZ(k)];
            acc[0][0] += a0 * bv.x; acc[0][1] += a0 * bv.y; acc[0][2] += a0 * bv.z; acc[0][3] += a0 * bv.w;
            acc[1][0] += a1 * bv.x; acc[1][1] += a1 * bv.y; acc[1][2] += a1 * bv.z; acc[1][3] += a1 * bv.w;
            acc[2][0] += a2 * bv.x; acc[2][1] += a2 * bv.y; acc[2][2] += a2 * bv.z; acc[2][3] += a2 * bv.w;
            acc[3][0] += a3 * bv.x; acc[3][1] += a3 * bv.y; acc[3][2] += a3 * bv.z; acc[3][3] += a3 * bv.w;
        }
        __syncthreads();
    }

    if (WRITE_PART) {
        float* p = dst + (size_t)(sliceOff + blockIdx.y) * 64 * N;
        #pragma unroll
        for (int i = 0; i < 4; ++i) {
            int m = ty * 4 + i;
            float4 v = make_float4(acc[i][0], acc[i][1], acc[i][2], acc[i][3]);
            *(float4*)&p[(size_t)m * N + n0 + tx * 4] = v;
        }
    } else {
        #pragma unroll
        for (int i = 0; i < 4; ++i) {
            int m = ty * 4 + i;
            int n = n0 + tx * 4;
            float4 v = make_float4(acc[i][0], acc[i][1], acc[i][2], acc[i][3]);
            if (bias) {
                v.x += bias[n + 0]; v.y += bias[n + 1];
                v.z += bias[n + 2]; v.w += bias[n + 3];
            }
            *(float4*)&dst[(size_t)m * N + n] = v;
        }
    }
}

// sum split-K partials + biases (+ optional tanh)
__global__ void reduce_parts(const float* __restrict__ parts, int nsl,
                             const float* __restrict__ b1, const float* __restrict__ b2,
                             float* __restrict__ C, int N, int act)
{
    int idx = blockIdx.x * 256 + threadIdx.x;
    float s = 0.f;
    for (int i = 0; i < nsl; ++i) s += parts[(size_t)i * 64 * N + idx];
    int n = idx % N;
    if (b1) s += b1[n];
    if (b2) s += b2[n];
    if (act) s = tanhf(s);
    C[idx] = s;
}

// embedding gather: g_x[b,h] = emb[seq[b], h]
__global__ void gather_k(const int* __restrict__ seq, const float* __restrict__ emb,
                         float* __restrict__ x)
{
    int idx = blockIdx.x * 256 + threadIdx.x;
    int b = idx >> 10;
    x[idx] = emb[(size_t)seq[b] * Hh + (idx & 1023)];
}

__device__ __forceinline__ float sigf(float x) { return 1.f / (1.f + expf(-x)); }

// LSTM pointwise: gates [64,4096] -> h_new, c_new (also stash h_new into g_cin)
__global__ void lstm_pw(const float* __restrict__ gates, const float* __restrict__ c0,
                        float* __restrict__ h_out, float* __restrict__ c_out,
                        float* __restrict__ cin)
{
    int idx = blockIdx.x * 256 + threadIdx.x;   // 64*1024
    int b = idx >> 10, h = idx & 1023;
    const float* gr = gates + (size_t)b * H4;
    float ig = sigf(gr[h]);
    float fg = sigf(gr[Hh + h]);
    float gg = tanhf(gr[2 * Hh + h]);
    float og = sigf(gr[3 * Hh + h]);
    float c = fg * c0[idx] + ig * gg;
    float hn = og * tanhf(c);
    c_out[idx] = c;
    h_out[idx] = hn;
    cin[(size_t)b * H3 + h] = hn;
}

// scores[b,s] = q[b,:] . enc[s,b,:]   (warp per (b,s))
__global__ void scores_k(const float* __restrict__ q, const float* __restrict__ enc,
                         float* __restrict__ sc)
{
    int b = blockIdx.y;
    int s = blockIdx.x * 8 + (threadIdx.x >> 5);
    int lane = threadIdx.x & 31;
    const float* e = enc + (size_t)s * (Bz * Ee) + (size_t)b * Ee;
    const float* qq = q + (size_t)b * Ee;
    float acc = 0.f;
    #pragma unroll 8
    for (int i = lane; i < Ee; i += 32) acc += qq[i] * e[i];
    #pragma unroll
    for (int o = 16; o; o >>= 1) acc += __shfl_xor_sync(0xffffffffu, acc, o);
    if (lane == 0) sc[b * Ss + s] = acc;
}

// softmax over S per batch; write both to d_out region and scratch
__global__ void softmax_k(const float* __restrict__ sc, float* __restrict__ aw_out,
                          float* __restrict__ aw_scr)
{
    __shared__ float red[Ss];
    int b = blockIdx.x, t = threadIdx.x;
    float v = sc[b * Ss + t];
    red[t] = v; __syncthreads();
    for (int o = 256; o; o >>= 1) { if (t < o) red[t] = fmaxf(red[t], red[t + o]); __syncthreads(); }
    float m = red[0]; __syncthreads();
    float e = expf(v - m);
    red[t] = e; __syncthreads();
    for (int o = 256; o; o >>= 1) { if (t < o) red[t] += red[t + o]; __syncthreads(); }
    float w = e / red[0];
    aw_out[b * Ss + t] = w;
    aw_scr[b * Ss + t] = w;
}

// context[b,e] = sum_s aw[b,s] * enc[s,b,e]  -> g_cin[b, 1024+e]
__global__ void context_k(const float* __restrict__ aw, const float* __restrict__ enc,
                          float* __restrict__ cin)
{
    __shared__ float w[Ss];
    int b = blockIdx.y;
    int e = blockIdx.x * 256 + threadIdx.x;
    w[threadIdx.x] = aw[b * Ss + threadIdx.x];
    w[256 + threadIdx.x] = aw[b * Ss + 256 + threadIdx.x];
    __syncthreads();
    const float* p = enc + (size_t)b * Ee + e;
    float acc = 0.f;
    #pragma unroll 8
    for (int s = 0; s < Ss; ++s) acc += w[s] * p[(size_t)s * (Bz * Ee)];
    cin[(size_t)b * H3 + Hh + e] = acc;
}

static float* sym(const void* s) {
    void* p = nullptr;
    cudaGetSymbolAddress(&p, s);
    return (float*)p;
}

extern "C" void kernel_launch(void* const* d_in, const int* in_sizes, int n_in,
                              void* d_out, int out_size)
{
    const int*   seq      = (const int*)  d_in[0];
    const float* h0       = (const float*)d_in[1];
    const float* c0       = (const float*)d_in[2];
    const float* enc      = (const float*)d_in[3];
    const float* emb      = (const float*)d_in[4];
    const float* w_ih     = (const float*)d_in[5];
    const float* w_hh     = (const float*)d_in[6];
    const float* b_ih     = (const float*)d_in[7];
    const float* b_hh     = (const float*)d_in[8];
    const float* attn_w   = (const float*)d_in[9];
    // d_in[10] = attn_b: constant over s -> cancels exactly in softmax (and is zero)
    const float* concat_w = (const float*)d_in[11];
    const float* concat_b = (const float*)d_in[12];
    const float* out_w    = (const float*)d_in[13];
    const float* out_b    = (const float*)d_in[14];

    float* out    = (float*)d_out;                    // [64, 32000]
    float* h_out  = out + (size_t)Bz * Vv;            // [1,64,1024]
    float* c_out  = h_out + Bz * Hh;                  // [1,64,1024]
    float* aw_out = c_out + Bz * Hh;                  // [64,1,512]

    float* px     = sym(g_x);
    float* ppart  = sym(g_part);
    float* pgates = sym(g_gates);
    float* pq     = sym(g_q);
    float* psc    = sym(g_scores);
    float* paw    = sym(g_aw);
    float* pcin   = sym(g_cin);
    float* pcc    = sym(g_cc);

    // 1. embedding gather
    gather_k<<<(Bz * Hh) / 256, 256>>>(seq, emb, px);

    // 2. LSTM gates: x @ w_ih.T (slices 0-3) + h0 @ w_hh.T (slices 4-7), split-K=4
    gemm_m64<0, true><<<dim3(H4 / 64, 4), 256>>>(px, w_ih, ppart, nullptr, H4, Hh, 4, 0);
    gemm_m64<0, true><<<dim3(H4 / 64, 4), 256>>>(h0, w_hh, ppart, nullptr, H4, Hh, 4, 4);
    reduce_parts<<<(Bz * H4) / 256, 256>>>(ppart, 8, b_ih, b_hh, pgates, H4, 0);
    lstm_pw<<<(Bz * Hh) / 256, 256>>>(pgates, c0, h_out, c_out, pcin);

    // 3. attention query q = h_new @ attn_w   (attn_w is [H,E], k-major), split-K=8
    gemm_m64<1, true><<<dim3(Ee / 64, 8), 256>>>(h_out, attn_w, ppart, nullptr, Ee, Hh, 2, 0);
    reduce_parts<<<(Bz * Ee) / 256, 256>>>(ppart, 8, nullptr, nullptr, pq, Ee, 0);

    // 4. scores + softmax + context
    scores_k<<<dim3(Ss / 8, Bz), 256>>>(pq, enc, psc);
    softmax_k<<<Bz, Ss>>>(psc, aw_out, paw);
    context_k<<<dim3(Ee / 256, Bz), 256>>>(paw, enc, pcin);

    // 5. concat GEMM + tanh: cc = tanh([h|ctx] @ concat_w.T + concat_b), split-K=4
    gemm_m64<0, true><<<dim3(H3 / 64, 4), 256>>>(pcin, concat_w, ppart, nullptr, H3, H3, 12, 0);
    reduce_parts<<<(Bz * H3) / 256, 256>>>(ppart, 4, concat_b, nullptr, pcc, H3, 1);

    // 6. vocab GEMM: out = cc @ out_w.T + out_b (direct, 500 blocks)
    gemm_m64<0, false><<<dim3(Vv / 64, 1), 256>>>(pcc, out_w, out, out_b, Vv, H3, H3 / 64, 0);
}

// round 5
// speedup vs baseline: 1.7400x; 1.7400x over previous
#include <cuda_runtime.h>
#include <cuda_bf16.h>
#include <math.h>
#include <cstdint>

// Shapes
#define Bz 64
#define Hh 1024
#define Vv 32000
#define Ss 512
#define Ee 2048   // 2H
#define H3 3072   // 3H
#define H4 4096   // 4H

// ---------------- scratch ----------------
__device__ __align__(16) float g_x[Bz * Hh];
__device__ __align__(16) float g_part[8 * Bz * H4];
__device__ __align__(16) float g_gates[Bz * H4];
__device__ __align__(16) float g_q[Bz * Ee];
__device__ __align__(16) float g_scores[Bz * Ss];
__device__ __align__(16) float g_aw[Bz * Ss];
__device__ __align__(16) float g_cin[Bz * H3];
__device__ __align__(16) float g_cc[Bz * H3];

// ================= vocab GEMM via mma.sync (bf16 3-split) =================
// out[b, v] = cc[b,:] . out_w[v,:] + out_b[v]
// CTA: 256 vocab rows (M) x 64 batch (N). 512 threads = 16 warps, warp tile 32x32.
#define KC 32
#define MT 256
#define SA 40              // A smem row stride in bf16 elems (padded vs 32)
#define SB 40
#define A_ELEMS (MT * SA)  // 10240
#define B_ELEMS (64 * SB)  // 2560
#define OFF_AHI 0
#define OFF_ALO (2 * A_ELEMS)            // 20480
#define OFF_BHI (4 * A_ELEMS)            // 40960
#define OFF_BLO (4 * A_ELEMS + 2 * B_ELEMS)  // 46080
#define SMEM_ELEMS (4 * A_ELEMS + 4 * B_ELEMS)  // 51200 bf16 = 102400 B
#define STG_STRIDE 66

__device__ __forceinline__ void mma16816(float c[4],
    uint32_t a0, uint32_t a1, uint32_t a2, uint32_t a3,
    uint32_t b0, uint32_t b1)
{
    asm volatile(
        "mma.sync.aligned.m16n8k16.row.col.f32.bf16.bf16.f32 "
        "{%0,%1,%2,%3}, {%4,%5,%6,%7}, {%8,%9}, {%0,%1,%2,%3};"
        : "+f"(c[0]), "+f"(c[1]), "+f"(c[2]), "+f"(c[3])
        : "r"(a0), "r"(a1), "r"(a2), "r"(a3), "r"(b0), "r"(b1));
}

__device__ __forceinline__ void cvt4(float4 v, __nv_bfloat16* hi, __nv_bfloat16* lo)
{
    __nv_bfloat16 hx = __float2bfloat16_rn(v.x);
    __nv_bfloat16 hy = __float2bfloat16_rn(v.y);
    __nv_bfloat16 hz = __float2bfloat16_rn(v.z);
    __nv_bfloat16 hw = __float2bfloat16_rn(v.w);
    __nv_bfloat162 h01 = __halves2bfloat162(hx, hy);
    __nv_bfloat162 h23 = __halves2bfloat162(hz, hw);
    *(uint2*)hi = make_uint2(*(uint32_t*)&h01, *(uint32_t*)&h23);
    __nv_bfloat162 l01 = __halves2bfloat162(
        __float2bfloat16_rn(v.x - __bfloat162float(hx)),
        __float2bfloat16_rn(v.y - __bfloat162float(hy)));
    __nv_bfloat162 l23 = __halves2bfloat162(
        __float2bfloat16_rn(v.z - __bfloat162float(hz)),
        __float2bfloat16_rn(v.w - __bfloat162float(hw)));
    *(uint2*)lo = make_uint2(*(uint32_t*)&l01, *(uint32_t*)&l23);
}

__global__ void __launch_bounds__(512, 1) vocab_mma(
    const float* __restrict__ outw, const float* __restrict__ cc,
    const float* __restrict__ outb, float* __restrict__ out)
{
    extern __shared__ __align__(16) __nv_bfloat16 sm[];

    const int tid  = threadIdx.x;
    const int lane = tid & 31;
    const int w    = tid >> 5;
    const int wm   = w & 7;       // m tile (32 rows)
    const int wn   = w >> 3;      // n tile (32 cols)
    const int v0   = blockIdx.x * MT;

    const int lm = tid >> 3;      // loader row 0..63
    const int cg = tid & 7;       // loader col group (4 floats)

    float acc[2][4][4];
    #pragma unroll
    for (int i = 0; i < 2; ++i)
        #pragma unroll
        for (int j = 0; j < 4; ++j)
            #pragma unroll
            for (int q = 0; q < 4; ++q) acc[i][j][q] = 0.f;

    float4 pa[4], pb;

    // ---- prime ----
    {
        int k0 = cg * 4;
        #pragma unroll
        for (int it = 0; it < 4; ++it)
            pa[it] = *(const float4*)&outw[(size_t)(v0 + it * 64 + lm) * H3 + k0];
        pb = *(const float4*)&cc[(size_t)lm * H3 + k0];
        #pragma unroll
        for (int it = 0; it < 4; ++it) {
            int m = it * 64 + lm;
            cvt4(pa[it], sm + OFF_AHI + m * SA + cg * 4, sm + OFF_ALO + m * SA + cg * 4);
        }
        cvt4(pb, sm + OFF_BHI + lm * SB + cg * 4, sm + OFF_BLO + lm * SB + cg * 4);
    }
    __syncthreads();

    const int rg = lane >> 2;
    const int kq = (lane & 3) * 2;

    for (int ch = 0; ch < 96; ++ch) {
        const int cur = ch & 1;
        // prefetch next chunk to regs
        if (ch < 95) {
            int k0 = (ch + 1) * KC + cg * 4;
            #pragma unroll
            for (int it = 0; it < 4; ++it)
                pa[it] = *(const float4*)&outw[(size_t)(v0 + it * 64 + lm) * H3 + k0];
            pb = *(const float4*)&cc[(size_t)lm * H3 + k0];
        }
        // mma on current buffer
        {
            const __nv_bfloat16* Ah = sm + OFF_AHI + cur * A_ELEMS + (wm * 32) * SA;
            const __nv_bfloat16* Al = sm + OFF_ALO + cur * A_ELEMS + (wm * 32) * SA;
            const __nv_bfloat16* Bh = sm + OFF_BHI + cur * B_ELEMS + (wn * 32) * SB;
            const __nv_bfloat16* Bl = sm + OFF_BLO + cur * B_ELEMS + (wn * 32) * SB;
            #pragma unroll
            for (int ks = 0; ks < KC; ks += 16) {
                const int ko = ks + kq;
                uint32_t ah[2][4], al[2][4], bh[4][2], bl[4][2];
                #pragma unroll
                for (int mt = 0; mt < 2; ++mt) {
                    const __nv_bfloat16* p = Ah + (mt * 16 + rg) * SA + ko;
                    ah[mt][0] = *(const uint32_t*)p;
                    ah[mt][1] = *(const uint32_t*)(p + 8 * SA);
                    ah[mt][2] = *(const uint32_t*)(p + 8);
                    ah[mt][3] = *(const uint32_t*)(p + 8 * SA + 8);
                    const __nv_bfloat16* q = Al + (mt * 16 + rg) * SA + ko;
                    al[mt][0] = *(const uint32_t*)q;
                    al[mt][1] = *(const uint32_t*)(q + 8 * SA);
                    al[mt][2] = *(const uint32_t*)(q + 8);
                    al[mt][3] = *(const uint32_t*)(q + 8 * SA + 8);
                }
                #pragma unroll
                for (int nt = 0; nt < 4; ++nt) {
                    const __nv_bfloat16* p = Bh + (nt * 8 + rg) * SB + ko;
                    bh[nt][0] = *(const uint32_t*)p;
                    bh[nt][1] = *(const uint32_t*)(p + 8);
                    const __nv_bfloat16* q = Bl + (nt * 8 + rg) * SB + ko;
                    bl[nt][0] = *(const uint32_t*)q;
                    bl[nt][1] = *(const uint32_t*)(q + 8);
                }
                #pragma unroll
                for (int mt = 0; mt < 2; ++mt)
                    #pragma unroll
                    for (int nt = 0; nt < 4; ++nt) {
                        mma16816(acc[mt][nt], ah[mt][0], ah[mt][1], ah[mt][2], ah[mt][3],
                                 bh[nt][0], bh[nt][1]);
                        mma16816(acc[mt][nt], ah[mt][0], ah[mt][1], ah[mt][2], ah[mt][3],
                                 bl[nt][0], bl[nt][1]);
                        mma16816(acc[mt][nt], al[mt][0], al[mt][1], al[mt][2], al[mt][3],
                                 bh[nt][0], bh[nt][1]);
                    }
            }
        }
        // convert prefetched regs into the other buffer
        if (ch < 95) {
            const int nxt = 1 - cur;
            #pragma unroll
            for (int it = 0; it < 4; ++it) {
                int m = it * 64 + lm;
                cvt4(pa[it], sm + OFF_AHI + nxt * A_ELEMS + m * SA + cg * 4,
                             sm + OFF_ALO + nxt * A_ELEMS + m * SA + cg * 4);
            }
            cvt4(pb, sm + OFF_BHI + nxt * B_ELEMS + lm * SB + cg * 4,
                     sm + OFF_BLO + nxt * B_ELEMS + lm * SB + cg * 4);
        }
        __syncthreads();
    }

    // ---- epilogue: regs -> smem stage [256][66] -> coalesced gmem ----
    float* stage = (float*)sm;
    #pragma unroll
    for (int mt = 0; mt < 2; ++mt)
        #pragma unroll
        for (int nt = 0; nt < 4; ++nt) {
            int row = wm * 32 + mt * 16 + rg;
            int col = wn * 32 + nt * 8 + kq;
            *(float2*)&stage[row * STG_STRIDE + col] =
                make_float2(acc[mt][nt][0], acc[mt][nt][1]);
            *(float2*)&stage[(row + 8) * STG_STRIDE + col] =
                make_float2(acc[mt][nt][2], acc[mt][nt][3]);
        }
    __syncthreads();

    {
        const int v  = tid & 255;                 // local vocab row
        const int b0 = (tid >> 8) * 32;           // batch base (0 or 32)
        const float bias = outb[v0 + v];
        #pragma unroll
        for (int j = 0; j < 32; ++j) {
            int b = b0 + j;
            out[(size_t)b * Vv + v0 + v] = stage[v * STG_STRIDE + b] + bias;
        }
    }
}

// ---------------- FFMA M=64 GEMM ----------------
#define SWZ(k) ((((k) >> 2) & 15) << 2)

template<int BLAYOUT, bool WRITE_PART>
__global__ void __launch_bounds__(256) gemm_m64(
    const float* __restrict__ A, const float* __restrict__ W,
    float* __restrict__ dst, const float* __restrict__ bias,
    int N, int K, int kChunks, int sliceOff)
{
    __shared__ __align__(16) float As[64][65];
    __shared__ __align__(16) float Bs[64][64];

    const int tid = threadIdx.x;
    const int tx = tid & 15;
    const int ty = tid >> 4;
    const int n0 = blockIdx.x * 64;
    const int kBase = blockIdx.y * kChunks * 64;

    float acc[4][4] = {};

    for (int c = 0; c < kChunks; ++c) {
        const int k0 = kBase + c * 64;
        #pragma unroll
        for (int it = 0; it < 4; ++it) {
            int lin = tid + it * 256;
            int m = lin >> 4, k4 = lin & 15;
            float4 v = *(const float4*)&A[(size_t)m * K + k0 + k4 * 4];
            As[m][k4 * 4 + 0] = v.x; As[m][k4 * 4 + 1] = v.y;
            As[m][k4 * 4 + 2] = v.z; As[m][k4 * 4 + 3] = v.w;
        }
        if (BLAYOUT == 0) {
            #pragma unroll
            for (int it = 0; it < 4; ++it) {
                int lin = tid + it * 256;
                int n = lin >> 4, k4 = lin & 15;
                float4 v = *(const float4*)&W[(size_t)(n0 + n) * K + k0 + k4 * 4];
                int k = k4 * 4;
                Bs[k + 0][n ^ SWZ(k + 0)] = v.x;
                Bs[k + 1][n ^ SWZ(k + 1)] = v.y;
                Bs[k + 2][n ^ SWZ(k + 2)] = v.z;
                Bs[k + 3][n ^ SWZ(k + 3)] = v.w;
            }
        } else {
            #pragma unroll
            for (int it = 0; it < 4; ++it) {
                int lin = tid + it * 256;
                int k = lin >> 4, n4 = lin & 15;
                float4 v = *(const float4*)&W[(size_t)(k0 + k) * N + n0 + n4 * 4];
                *(float4*)&Bs[k][(n4 * 4) ^ SWZ(k)] = v;
            }
        }
        __syncthreads();
        #pragma unroll 16
        for (int k = 0; k < 64; ++k) {
            float a0 = As[ty * 4 + 0][k];
            float a1 = As[ty * 4 + 1][k];
            float a2 = As[ty * 4 + 2][k];
            float a3 = As[ty * 4 + 3][k];
            float4 bv = *(const float4*)&Bs[k][(tx * 4) ^ SWZ(k)];
            acc[0][0] += a0 * bv.x; acc[0][1] += a0 * bv.y; acc[0][2] += a0 * bv.z; acc[0][3] += a0 * bv.w;
            acc[1][0] += a1 * bv.x; acc[1][1] += a1 * bv.y; acc[1][2] += a1 * bv.z; acc[1][3] += a1 * bv.w;
            acc[2][0] += a2 * bv.x; acc[2][1] += a2 * bv.y; acc[2][2] += a2 * bv.z; acc[2][3] += a2 * bv.w;
            acc[3][0] += a3 * bv.x; acc[3][1] += a3 * bv.y; acc[3][2] += a3 * bv.z; acc[3][3] += a3 * bv.w;
        }
        __syncthreads();
    }

    if (WRITE_PART) {
        float* p = dst + (size_t)(sliceOff + blockIdx.y) * 64 * N;
        #pragma unroll
        for (int i = 0; i < 4; ++i) {
            int m = ty * 4 + i;
            float4 v = make_float4(acc[i][0], acc[i][1], acc[i][2], acc[i][3]);
            *(float4*)&p[(size_t)m * N + n0 + tx * 4] = v;
        }
    } else {
        #pragma unroll
        for (int i = 0; i < 4; ++i) {
            int m = ty * 4 + i;
            int n = n0 + tx * 4;
            float4 v = make_float4(acc[i][0], acc[i][1], acc[i][2], acc[i][3]);
            if (bias) {
                v.x += bias[n + 0]; v.y += bias[n + 1];
                v.z += bias[n + 2]; v.w += bias[n + 3];
            }
            *(float4*)&dst[(size_t)m * N + n] = v;
        }
    }
}

__global__ void reduce_parts(const float* __restrict__ parts, int nsl,
                             const float* __restrict__ b1, const float* __restrict__ b2,
                             float* __restrict__ C, int N, int act)
{
    int idx = blockIdx.x * 256 + threadIdx.x;
    float s = 0.f;
    for (int i = 0; i < nsl; ++i) s += parts[(size_t)i * 64 * N + idx];
    int n = idx % N;
    if (b1) s += b1[n];
    if (b2) s += b2[n];
    if (act) s = tanhf(s);
    C[idx] = s;
}

__global__ void gather_k(const int* __restrict__ seq, const float* __restrict__ emb,
                         float* __restrict__ x)
{
    int idx = blockIdx.x * 256 + threadIdx.x;
    int b = idx >> 10;
    x[idx] = emb[(size_t)seq[b] * Hh + (idx & 1023)];
}

__device__ __forceinline__ float sigf(float x) { return 1.f / (1.f + expf(-x)); }

__global__ void lstm_pw(const float* __restrict__ gates, const float* __restrict__ c0,
                        float* __restrict__ h_out, float* __restrict__ c_out,
                        float* __restrict__ cin)
{
    int idx = blockIdx.x * 256 + threadIdx.x;
    int b = idx >> 10, h = idx & 1023;
    const float* gr = gates + (size_t)b * H4;
    float ig = sigf(gr[h]);
    float fg = sigf(gr[Hh + h]);
    float gg = tanhf(gr[2 * Hh + h]);
    float og = sigf(gr[3 * Hh + h]);
    float c = fg * c0[idx] + ig * gg;
    float hn = og * tanhf(c);
    c_out[idx] = c;
    h_out[idx] = hn;
    cin[(size_t)b * H3 + h] = hn;
}

__global__ void scores_k(const float* __restrict__ q, const float* __restrict__ enc,
                         float* __restrict__ sc)
{
    int b = blockIdx.y;
    int s = blockIdx.x * 8 + (threadIdx.x >> 5);
    int lane = threadIdx.x & 31;
    const float* e = enc + (size_t)s * (Bz * Ee) + (size_t)b * Ee;
    const float* qq = q + (size_t)b * Ee;
    float acc = 0.f;
    #pragma unroll 8
    for (int i = lane; i < Ee; i += 32) acc += qq[i] * e[i];
    #pragma unroll
    for (int o = 16; o; o >>= 1) acc += __shfl_xor_sync(0xffffffffu, acc, o);
    if (lane == 0) sc[b * Ss + s] = acc;
}

__global__ void softmax_k(const float* __restrict__ sc, float* __restrict__ aw_out,
                          float* __restrict__ aw_scr)
{
    __shared__ float red[Ss];
    int b = blockIdx.x, t = threadIdx.x;
    float v = sc[b * Ss + t];
    red[t] = v; __syncthreads();
    for (int o = 256; o; o >>= 1) { if (t < o) red[t] = fmaxf(red[t], red[t + o]); __syncthreads(); }
    float m = red[0]; __syncthreads();
    float e = expf(v - m);
    red[t] = e; __syncthreads();
    for (int o = 256; o; o >>= 1) { if (t < o) red[t] += red[t + o]; __syncthreads(); }
    float w = e / red[0];
    aw_out[b * Ss + t] = w;
    aw_scr[b * Ss + t] = w;
}

__global__ void context_k(const float* __restrict__ aw, const float* __restrict__ enc,
                          float* __restrict__ cin)
{
    __shared__ float w[Ss];
    int b = blockIdx.y;
    int e = blockIdx.x * 256 + threadIdx.x;
    w[threadIdx.x] = aw[b * Ss + threadIdx.x];
    w[256 + threadIdx.x] = aw[b * Ss + 256 + threadIdx.x];
    __syncthreads();
    const float* p = enc + (size_t)b * Ee + e;
    float acc = 0.f;
    #pragma unroll 8
    for (int s = 0; s < Ss; ++s) acc += w[s] * p[(size_t)s * (Bz * Ee)];
    cin[(size_t)b * H3 + Hh + e] = acc;
}

static float* sym(const void* s) {
    void* p = nullptr;
    cudaGetSymbolAddress(&p, s);
    return (float*)p;
}

extern "C" void kernel_launch(void* const* d_in, const int* in_sizes, int n_in,
                              void* d_out, int out_size)
{
    const int*   seq      = (const int*)  d_in[0];
    const float* h0       = (const float*)d_in[1];
    const float* c0       = (const float*)d_in[2];
    const float* enc      = (const float*)d_in[3];
    const float* emb      = (const float*)d_in[4];
    const float* w_ih     = (const float*)d_in[5];
    const float* w_hh     = (const float*)d_in[6];
    const float* b_ih     = (const float*)d_in[7];
    const float* b_hh     = (const float*)d_in[8];
    const float* attn_w   = (const float*)d_in[9];
    const float* concat_w = (const float*)d_in[11];
    const float* concat_b = (const float*)d_in[12];
    const float* out_w    = (const float*)d_in[13];
    const float* out_b    = (const float*)d_in[14];

    float* out    = (float*)d_out;
    float* h_out  = out + (size_t)Bz * Vv;
    float* c_out  = h_out + Bz * Hh;
    float* aw_out = c_out + Bz * Hh;

    float* px     = sym(g_x);
    float* ppart  = sym(g_part);
    float* pgates = sym(g_gates);
    float* pq     = sym(g_q);
    float* psc    = sym(g_scores);
    float* paw    = sym(g_aw);
    float* pcin   = sym(g_cin);
    float* pcc    = sym(g_cc);

    cudaFuncSetAttribute(vocab_mma, cudaFuncAttributeMaxDynamicSharedMemorySize,
                         SMEM_ELEMS * 2);

    // 1. embedding
    gather_k<<<(Bz * Hh) / 256, 256>>>(seq, emb, px);

    // 2. LSTM
    gemm_m64<0, true><<<dim3(H4 / 64, 4), 256>>>(px, w_ih, ppart, nullptr, H4, Hh, 4, 0);
    gemm_m64<0, true><<<dim3(H4 / 64, 4), 256>>>(h0, w_hh, ppart, nullptr, H4, Hh, 4, 4);
    reduce_parts<<<(Bz * H4) / 256, 256>>>(ppart, 8, b_ih, b_hh, pgates, H4, 0);
    lstm_pw<<<(Bz * Hh) / 256, 256>>>(pgates, c0, h_out, c_out, pcin);

    // 3. attention query
    gemm_m64<1, true><<<dim3(Ee / 64, 8), 256>>>(h_out, attn_w, ppart, nullptr, Ee, Hh, 2, 0);
    reduce_parts<<<(Bz * Ee) / 256, 256>>>(ppart, 8, nullptr, nullptr, pq, Ee, 0);

    // 4. scores + softmax + context
    scores_k<<<dim3(Ss / 8, Bz), 256>>>(pq, enc, psc);
    softmax_k<<<Bz, Ss>>>(psc, aw_out, paw);
    context_k<<<dim3(Ee / 256, Bz), 256>>>(paw, enc, pcin);

    // 5. concat GEMM + tanh
    gemm_m64<0, true><<<dim3(H3 / 64, 4), 256>>>(pcin, concat_w, ppart, nullptr, H3, H3, 12, 0);
    reduce_parts<<<(Bz * H3) / 256, 256>>>(ppart, 4, concat_b, nullptr, pcc, H3, 1);

    // 6. vocab GEMM on tensor cores (mma.sync bf16 3-split)
    vocab_mma<<<Vv / MT, 512, SMEM_ELEMS * 2>>>(out_w, pcc, out_b, out);
}

// round 6
// speedup vs baseline: 2.0433x; 1.1743x over previous
#include <cuda_runtime.h>
#include <cuda_bf16.h>
#include <math.h>
#include <cstdint>

// Shapes
#define Bz 64
#define Hh 1024
#define Vv 32000
#define Ss 512
#define Ee 2048   // 2H
#define H3 3072   // 3H
#define H4 4096   // 4H

// ---------------- scratch ----------------
__device__ __align__(16) float g_x[Bz * Hh];
__device__ __align__(16) float g_part[8 * Bz * H4];
__device__ __align__(16) float g_gates[Bz * H4];
__device__ __align__(16) float g_q[Bz * Ee];
__device__ __align__(16) float g_scores[Bz * Ss];
__device__ __align__(16) float g_cin[Bz * H3];
__device__ __align__(16) float g_cc[Bz * H3];
__device__ __align__(16) float g_ctxp[4 * Bz * Ee];   // split context partials
__device__ __align__(16) float g_ml[4 * Bz * 2];      // split (m, l)

// ================= common mma helpers =================
__device__ __forceinline__ void mma16816(float c[4],
    uint32_t a0, uint32_t a1, uint32_t a2, uint32_t a3,
    uint32_t b0, uint32_t b1)
{
    asm volatile(
        "mma.sync.aligned.m16n8k16.row.col.f32.bf16.bf16.f32 "
        "{%0,%1,%2,%3}, {%4,%5,%6,%7}, {%8,%9}, {%0,%1,%2,%3};"
        : "+f"(c[0]), "+f"(c[1]), "+f"(c[2]), "+f"(c[3])
        : "r"(a0), "r"(a1), "r"(a2), "r"(a3), "r"(b0), "r"(b1));
}

__device__ __forceinline__ void cvt4(float4 v, __nv_bfloat16* hi, __nv_bfloat16* lo)
{
    __nv_bfloat16 hx = __float2bfloat16_rn(v.x);
    __nv_bfloat16 hy = __float2bfloat16_rn(v.y);
    __nv_bfloat16 hz = __float2bfloat16_rn(v.z);
    __nv_bfloat16 hw = __float2bfloat16_rn(v.w);
    __nv_bfloat162 h01 = __halves2bfloat162(hx, hy);
    __nv_bfloat162 h23 = __halves2bfloat162(hz, hw);
    *(uint2*)hi = make_uint2(*(uint32_t*)&h01, *(uint32_t*)&h23);
    __nv_bfloat162 l01 = __halves2bfloat162(
        __float2bfloat16_rn(v.x - __bfloat162float(hx)),
        __float2bfloat16_rn(v.y - __bfloat162float(hy)));
    __nv_bfloat162 l23 = __halves2bfloat162(
        __float2bfloat16_rn(v.z - __bfloat162float(hz)),
        __float2bfloat16_rn(v.w - __bfloat162float(hw)));
    *(uint2*)lo = make_uint2(*(uint32_t*)&l01, *(uint32_t*)&l23);
}

// ================= vocab GEMM (unchanged from R5, passes) =================
#define KC 32
#define MT 256
#define SA 40
#define SB 40
#define A_ELEMS (MT * SA)
#define B_ELEMS (64 * SB)
#define OFF_AHI 0
#define OFF_ALO (2 * A_ELEMS)
#define OFF_BHI (4 * A_ELEMS)
#define OFF_BLO (4 * A_ELEMS + 2 * B_ELEMS)
#define SMEM_ELEMS (4 * A_ELEMS + 4 * B_ELEMS)
#define STG_STRIDE 66

__global__ void __launch_bounds__(512, 1) vocab_mma(
    const float* __restrict__ outw, const float* __restrict__ cc,
    const float* __restrict__ outb, float* __restrict__ out)
{
    extern __shared__ __align__(16) __nv_bfloat16 sm[];

    const int tid  = threadIdx.x;
    const int lane = tid & 31;
    const int w    = tid >> 5;
    const int wm   = w & 7;
    const int wn   = w >> 3;
    const int v0   = blockIdx.x * MT;

    const int lm = tid >> 3;
    const int cg = tid & 7;

    float acc[2][4][4];
    #pragma unroll
    for (int i = 0; i < 2; ++i)
        #pragma unroll
        for (int j = 0; j < 4; ++j)
            #pragma unroll
            for (int q = 0; q < 4; ++q) acc[i][j][q] = 0.f;

    float4 pa[4], pb;

    {
        int k0 = cg * 4;
        #pragma unroll
        for (int it = 0; it < 4; ++it)
            pa[it] = *(const float4*)&outw[(size_t)(v0 + it * 64 + lm) * H3 + k0];
        pb = *(const float4*)&cc[(size_t)lm * H3 + k0];
        #pragma unroll
        for (int it = 0; it < 4; ++it) {
            int m = it * 64 + lm;
            cvt4(pa[it], sm + OFF_AHI + m * SA + cg * 4, sm + OFF_ALO + m * SA + cg * 4);
        }
        cvt4(pb, sm + OFF_BHI + lm * SB + cg * 4, sm + OFF_BLO + lm * SB + cg * 4);
    }
    __syncthreads();

    const int rg = lane >> 2;
    const int kq = (lane & 3) * 2;

    for (int ch = 0; ch < 96; ++ch) {
        const int cur = ch & 1;
        if (ch < 95) {
            int k0 = (ch + 1) * KC + cg * 4;
            #pragma unroll
            for (int it = 0; it < 4; ++it)
                pa[it] = *(const float4*)&outw[(size_t)(v0 + it * 64 + lm) * H3 + k0];
            pb = *(const float4*)&cc[(size_t)lm * H3 + k0];
        }
        {
            const __nv_bfloat16* Ah = sm + OFF_AHI + cur * A_ELEMS + (wm * 32) * SA;
            const __nv_bfloat16* Al = sm + OFF_ALO + cur * A_ELEMS + (wm * 32) * SA;
            const __nv_bfloat16* Bh = sm + OFF_BHI + cur * B_ELEMS + (wn * 32) * SB;
            const __nv_bfloat16* Bl = sm + OFF_BLO + cur * B_ELEMS + (wn * 32) * SB;
            #pragma unroll
            for (int ks = 0; ks < KC; ks += 16) {
                const int ko = ks + kq;
                uint32_t ah[2][4], al[2][4], bh[4][2], bl[4][2];
                #pragma unroll
                for (int mt = 0; mt < 2; ++mt) {
                    const __nv_bfloat16* p = Ah + (mt * 16 + rg) * SA + ko;
                    ah[mt][0] = *(const uint32_t*)p;
                    ah[mt][1] = *(const uint32_t*)(p + 8 * SA);
                    ah[mt][2] = *(const uint32_t*)(p + 8);
                    ah[mt][3] = *(const uint32_t*)(p + 8 * SA + 8);
                    const __nv_bfloat16* q = Al + (mt * 16 + rg) * SA + ko;
                    al[mt][0] = *(const uint32_t*)q;
                    al[mt][1] = *(const uint32_t*)(q + 8 * SA);
                    al[mt][2] = *(const uint32_t*)(q + 8);
                    al[mt][3] = *(const uint32_t*)(q + 8 * SA + 8);
                }
                #pragma unroll
                for (int nt = 0; nt < 4; ++nt) {
                    const __nv_bfloat16* p = Bh + (nt * 8 + rg) * SB + ko;
                    bh[nt][0] = *(const uint32_t*)p;
                    bh[nt][1] = *(const uint32_t*)(p + 8);
                    const __nv_bfloat16* q = Bl + (nt * 8 + rg) * SB + ko;
                    bl[nt][0] = *(const uint32_t*)q;
                    bl[nt][1] = *(const uint32_t*)(q + 8);
                }
                #pragma unroll
                for (int mt = 0; mt < 2; ++mt)
                    #pragma unroll
                    for (int nt = 0; nt < 4; ++nt) {
                        mma16816(acc[mt][nt], ah[mt][0], ah[mt][1], ah[mt][2], ah[mt][3],
                                 bh[nt][0], bh[nt][1]);
                        mma16816(acc[mt][nt], ah[mt][0], ah[mt][1], ah[mt][2], ah[mt][3],
                                 bl[nt][0], bl[nt][1]);
                        mma16816(acc[mt][nt], al[mt][0], al[mt][1], al[mt][2], al[mt][3],
                                 bh[nt][0], bh[nt][1]);
                    }
            }
        }
        if (ch < 95) {
            const int nxt = 1 - cur;
            #pragma unroll
            for (int it = 0; it < 4; ++it) {
                int m = it * 64 + lm;
                cvt4(pa[it], sm + OFF_AHI + nxt * A_ELEMS + m * SA + cg * 4,
                             sm + OFF_ALO + nxt * A_ELEMS + m * SA + cg * 4);
            }
            cvt4(pb, sm + OFF_BHI + nxt * B_ELEMS + lm * SB + cg * 4,
                     sm + OFF_BLO + nxt * B_ELEMS + lm * SB + cg * 4);
        }
        __syncthreads();
    }

    float* stage = (float*)sm;
    #pragma unroll
    for (int mt = 0; mt < 2; ++mt)
        #pragma unroll
        for (int nt = 0; nt < 4; ++nt) {
            int row = wm * 32 + mt * 16 + rg;
            int col = wn * 32 + nt * 8 + kq;
            *(float2*)&stage[row * STG_STRIDE + col] =
                make_float2(acc[mt][nt][0], acc[mt][nt][1]);
            *(float2*)&stage[(row + 8) * STG_STRIDE + col] =
                make_float2(acc[mt][nt][2], acc[mt][nt][3]);
        }
    __syncthreads();

    {
        const int v  = tid & 255;
        const int b0 = (tid >> 8) * 32;
        const float bias = outb[v0 + v];
        #pragma unroll
        for (int j = 0; j < 32; ++j) {
            int b = b0 + j;
            out[(size_t)b * Vv + v0 + v] = stage[v * STG_STRIDE + b] + bias;
        }
    }
}

// ================= generic small GEMM on mma.sync (split-K partials) =================
// parts[slice][b][n0+v] = sum_{k in slice} act[b,k] * Wrow[v,k]
// BLAYOUT 0: W is [N, K] (k-contiguous rows). BLAYOUT 1: W is [K, N] (transpose on store).
#define GSA 40
#define GA_EL (128 * GSA)   // 5120
#define GB_EL (64 * GSA)    // 2560
#define G_AHI 0
#define G_ALO (2 * GA_EL)
#define G_BHI (4 * GA_EL)
#define G_BLO (4 * GA_EL + 2 * GB_EL)
#define G_SMEM_BYTES ((4 * GA_EL + 4 * GB_EL) * 2)   // 61440

template<int BLAYOUT>
__global__ void __launch_bounds__(256, 1) mma_gemm(
    const float* __restrict__ W, const float* __restrict__ act,
    float* __restrict__ parts, int N, int K, int kChunks)
{
    extern __shared__ __align__(16) __nv_bfloat16 gsm[];
    const int tid  = threadIdx.x;
    const int lane = tid & 31;
    const int w    = tid >> 5;
    const int wm   = w & 3;        // 4 m tiles of 32 (MT=128)
    const int wn   = w >> 2;       // 2 n tiles of 32 (batch 64)
    const int n0   = blockIdx.x * 128;
    const int kBase = blockIdx.y * kChunks * KC;

    float acc[2][4][4];
    #pragma unroll
    for (int i = 0; i < 2; ++i)
        #pragma unroll
        for (int j = 0; j < 4; ++j)
            #pragma unroll
            for (int q = 0; q < 4; ++q) acc[i][j][q] = 0.f;

    float4 pa[4], pbv[2];
    const int ar = tid >> 3;     // 0..31
    const int cg = tid & 7;

    // --- load chunk k0 into regs ---
    auto loadAB = [&](int k0) {
        if (BLAYOUT == 0) {
            #pragma unroll
            for (int it = 0; it < 4; ++it)
                pa[it] = *(const float4*)&W[(size_t)(n0 + ar + it * 32) * K + k0 + cg * 4];
        } else {
            #pragma unroll
            for (int it = 0; it < 4; ++it)
                pa[it] = *(const float4*)&W[(size_t)(k0 + ar) * N + n0 + (cg + it * 8) * 4];
        }
        pbv[0] = *(const float4*)&act[(size_t)ar * K + k0 + cg * 4];
        pbv[1] = *(const float4*)&act[(size_t)(ar + 32) * K + k0 + cg * 4];
    };
    // --- convert regs into buffer buf ---
    auto storeAB = [&](int buf) {
        __nv_bfloat16* AH = gsm + G_AHI + buf * GA_EL;
        __nv_bfloat16* AL = gsm + G_ALO + buf * GA_EL;
        if (BLAYOUT == 0) {
            #pragma unroll
            for (int it = 0; it < 4; ++it) {
                int m = ar + it * 32;
                cvt4(pa[it], AH + m * GSA + cg * 4, AL + m * GSA + cg * 4);
            }
        } else {
            #pragma unroll
            for (int it = 0; it < 4; ++it) {
                int ng = cg + it * 8;
                float vv[4] = { pa[it].x, pa[it].y, pa[it].z, pa[it].w };
                #pragma unroll
                for (int f = 0; f < 4; ++f) {
                    int m = ng * 4 + f;
                    __nv_bfloat16 h = __float2bfloat16_rn(vv[f]);
                    AH[m * GSA + ar] = h;
                    AL[m * GSA + ar] = __float2bfloat16_rn(vv[f] - __bfloat162float(h));
                }
            }
        }
        __nv_bfloat16* BH = gsm + G_BHI + buf * GB_EL;
        __nv_bfloat16* BL = gsm + G_BLO + buf * GB_EL;
        cvt4(pbv[0], BH + ar * GSA + cg * 4, BL + ar * GSA + cg * 4);
        cvt4(pbv[1], BH + (ar + 32) * GSA + cg * 4, BL + (ar + 32) * GSA + cg * 4);
    };

    loadAB(kBase);
    storeAB(0);
    __syncthreads();

    const int rg = lane >> 2;
    const int kq = (lane & 3) * 2;

    for (int ch = 0; ch < kChunks; ++ch) {
        const int cur = ch & 1;
        if (ch + 1 < kChunks) loadAB(kBase + (ch + 1) * KC);
        {
            const __nv_bfloat16* Ah = gsm + G_AHI + cur * GA_EL + (wm * 32) * GSA;
            const __nv_bfloat16* Al = gsm + G_ALO + cur * GA_EL + (wm * 32) * GSA;
            const __nv_bfloat16* Bh = gsm + G_BHI + cur * GB_EL + (wn * 32) * GSA;
            const __nv_bfloat16* Bl = gsm + G_BLO + cur * GB_EL + (wn * 32) * GSA;
            #pragma unroll
            for (int ks = 0; ks < KC; ks += 16) {
                const int ko = ks + kq;
                uint32_t ah[2][4], al[2][4], bh[4][2], bl[4][2];
                #pragma unroll
                for (int mt = 0; mt < 2; ++mt) {
                    const __nv_bfloat16* p = Ah + (mt * 16 + rg) * GSA + ko;
                    ah[mt][0] = *(const uint32_t*)p;
                    ah[mt][1] = *(const uint32_t*)(p + 8 * GSA);
                    ah[mt][2] = *(const uint32_t*)(p + 8);
                    ah[mt][3] = *(const uint32_t*)(p + 8 * GSA + 8);
                    const __nv_bfloat16* q = Al + (mt * 16 + rg) * GSA + ko;
                    al[mt][0] = *(const uint32_t*)q;
                    al[mt][1] = *(const uint32_t*)(q + 8 * GSA);
                    al[mt][2] = *(const uint32_t*)(q + 8);
                    al[mt][3] = *(const uint32_t*)(q + 8 * GSA + 8);
                }
                #pragma unroll
                for (int nt = 0; nt < 4; ++nt) {
                    const __nv_bfloat16* p = Bh + (nt * 8 + rg) * GSA + ko;
                    bh[nt][0] = *(const uint32_t*)p;
                    bh[nt][1] = *(const uint32_t*)(p + 8);
                    const __nv_bfloat16* q = Bl + (nt * 8 + rg) * GSA + ko;
                    bl[nt][0] = *(const uint32_t*)q;
                    bl[nt][1] = *(const uint32_t*)(q + 8);
                }
                #pragma unroll
                for (int mt = 0; mt < 2; ++mt)
                    #pragma unroll
                    for (int nt = 0; nt < 4; ++nt) {
                        mma16816(acc[mt][nt], ah[mt][0], ah[mt][1], ah[mt][2], ah[mt][3],
                                 bh[nt][0], bh[nt][1]);
                        mma16816(acc[mt][nt], ah[mt][0], ah[mt][1], ah[mt][2], ah[mt][3],
                                 bl[nt][0], bl[nt][1]);
                        mma16816(acc[mt][nt], al[mt][0], al[mt][1], al[mt][2], al[mt][3],
                                 bh[nt][0], bh[nt][1]);
                    }
            }
        }
        if (ch + 1 < kChunks) storeAB(1 - cur);
        __syncthreads();
    }

    // epilogue: stage 128x64 fp32, then coalesced partial write
    float* stage = (float*)gsm;
    #pragma unroll
    for (int mt = 0; mt < 2; ++mt)
        #pragma unroll
        for (int nt = 0; nt < 4; ++nt) {
            int row = wm * 32 + mt * 16 + rg;
            int col = wn * 32 + nt * 8 + kq;
            *(float2*)&stage[row * STG_STRIDE + col] =
                make_float2(acc[mt][nt][0], acc[mt][nt][1]);
            *(float2*)&stage[(row + 8) * STG_STRIDE + col] =
                make_float2(acc[mt][nt][2], acc[mt][nt][3]);
        }
    __syncthreads();

    {
        float* p = parts + (size_t)blockIdx.y * 64 * N;
        const int v  = tid & 127;
        const int b0 = (tid >> 7) * 32;
        #pragma unroll
        for (int j = 0; j < 32; ++j) {
            int b = b0 + j;
            p[(size_t)b * N + n0 + v] = stage[v * STG_STRIDE + b];
        }
    }
}

// ================= split-K reduce (+bias, +tanh) =================
__global__ void reduce_parts(const float* __restrict__ parts, int nsl,
                             const float* __restrict__ b1, const float* __restrict__ b2,
                             float* __restrict__ C, int N, int act)
{
    int idx = blockIdx.x * 256 + threadIdx.x;
    float s = 0.f;
    for (int i = 0; i < nsl; ++i) s += parts[(size_t)i * 64 * N + idx];
    int n = idx % N;
    if (b1) s += b1[n];
    if (b2) s += b2[n];
    if (act) s = tanhf(s);
    C[idx] = s;
}

// ================= pointwise =================
__global__ void gather_k(const int* __restrict__ seq, const float* __restrict__ emb,
                         float* __restrict__ x)
{
    int idx = blockIdx.x * 256 + threadIdx.x;
    int b = idx >> 10;
    x[idx] = emb[(size_t)seq[b] * Hh + (idx & 1023)];
}

__device__ __forceinline__ float sigf(float x) { return 1.f / (1.f + expf(-x)); }

__global__ void lstm_pw(const float* __restrict__ gates, const float* __restrict__ c0,
                        float* __restrict__ h_out, float* __restrict__ c_out,
                        float* __restrict__ cin)
{
    int idx = blockIdx.x * 256 + threadIdx.x;
    int b = idx >> 10, h = idx & 1023;
    const float* gr = gates + (size_t)b * H4;
    float ig = sigf(gr[h]);
    float fg = sigf(gr[Hh + h]);
    float gg = tanhf(gr[2 * Hh + h]);
    float og = sigf(gr[3 * Hh + h]);
    float c = fg * c0[idx] + ig * gg;
    float hn = og * tanhf(c);
    c_out[idx] = c;
    h_out[idx] = hn;
    cin[(size_t)b * H3 + h] = hn;
}

// ================= single-pass split-S attention =================
// grid (4 splits, 64 b), 256 threads. Each block: 128 encoder positions, one enc pass.
__global__ void __launch_bounds__(256) att_split(
    const float* __restrict__ q, const float* __restrict__ enc,
    float* __restrict__ scores, float* __restrict__ ctxp, float* __restrict__ ml)
{
    __shared__ float wsum[2][8];
    const int b = blockIdx.y, sp = blockIdx.x;
    const int tid = threadIdx.x, lane = tid & 31, w = tid >> 5;
    const int e0 = tid * 4;

    const float* qb = q + (size_t)b * Ee;
    float4 q0 = *(const float4*)&qb[e0];
    float4 q1 = *(const float4*)&qb[1024 + e0];

    float m = -INFINITY, l = 0.f;
    float4 c0 = make_float4(0.f, 0.f, 0.f, 0.f);
    float4 c1 = make_float4(0.f, 0.f, 0.f, 0.f);

    const int sBeg = sp * 128, sEnd = sBeg + 128;
    const float* base = enc + (size_t)b * Ee + e0;

    float4 e0v = *(const float4*)&base[(size_t)sBeg * (Bz * Ee)];
    float4 e1v = *(const float4*)&base[(size_t)sBeg * (Bz * Ee) + 1024];

    for (int s = sBeg; s < sEnd; ++s) {
        float4 n0v, n1v;
        if (s + 1 < sEnd) {
            n0v = *(const float4*)&base[(size_t)(s + 1) * (Bz * Ee)];
            n1v = *(const float4*)&base[(size_t)(s + 1) * (Bz * Ee) + 1024];
        }
        float d = q0.x * e0v.x + q0.y * e0v.y + q0.z * e0v.z + q0.w * e0v.w
                + q1.x * e1v.x + q1.y * e1v.y + q1.z * e1v.z + q1.w * e1v.w;
        #pragma unroll
        for (int o = 16; o; o >>= 1) d += __shfl_xor_sync(0xffffffffu, d, o);
        if (lane == 0) wsum[s & 1][w] = d;
        __syncthreads();
        float sc = wsum[s & 1][0] + wsum[s & 1][1] + wsum[s & 1][2] + wsum[s & 1][3]
                 + wsum[s & 1][4] + wsum[s & 1][5] + wsum[s & 1][6] + wsum[s & 1][7];
        if (tid == 0) scores[b * Ss + s] = sc;
        float mn = fmaxf(m, sc);
        float scale = __expf(m - mn);       // first iter: exp(-inf) = 0
        float pw = __expf(sc - mn);
        l = l * scale + pw;
        c0.x = c0.x * scale + pw * e0v.x;
        c0.y = c0.y * scale + pw * e0v.y;
        c0.z = c0.z * scale + pw * e0v.z;
        c0.w = c0.w * scale + pw * e0v.w;
        c1.x = c1.x * scale + pw * e1v.x;
        c1.y = c1.y * scale + pw * e1v.y;
        c1.z = c1.z * scale + pw * e1v.z;
        c1.w = c1.w * scale + pw * e1v.w;
        m = mn;
        e0v = n0v; e1v = n1v;
    }

    float* cp = ctxp + ((size_t)sp * Bz + b) * Ee;
    *(float4*)&cp[e0] = c0;
    *(float4*)&cp[1024 + e0] = c1;
    if (tid == 0) {
        ml[(sp * Bz + b) * 2 + 0] = m;
        ml[(sp * Bz + b) * 2 + 1] = l;
    }
}

__global__ void __launch_bounds__(256) att_combine(
    const float* __restrict__ ctxp, const float* __restrict__ ml,
    const float* __restrict__ scores, float* __restrict__ cin,
    float* __restrict__ aw_out)
{
    const int b = blockIdx.x, tid = threadIdx.x;
    float m0 = ml[(0 * Bz + b) * 2], l0 = ml[(0 * Bz + b) * 2 + 1];
    float m1 = ml[(1 * Bz + b) * 2], l1 = ml[(1 * Bz + b) * 2 + 1];
    float m2 = ml[(2 * Bz + b) * 2], l2 = ml[(2 * Bz + b) * 2 + 1];
    float m3 = ml[(3 * Bz + b) * 2], l3 = ml[(3 * Bz + b) * 2 + 1];
    float M = fmaxf(fmaxf(m0, m1), fmaxf(m2, m3));
    float w0 = __expf(m0 - M), w1 = __expf(m1 - M);
    float w2 = __expf(m2 - M), w3 = __expf(m3 - M);
    float L = l0 * w0 + l1 * w1 + l2 * w2 + l3 * w3;
    float invL = 1.f / L;

    for (int e = tid; e < Ee; e += 256) {
        float v = ctxp[((size_t)0 * Bz + b) * Ee + e] * w0
                + ctxp[((size_t)1 * Bz + b) * Ee + e] * w1
                + ctxp[((size_t)2 * Bz + b) * Ee + e] * w2
                + ctxp[((size_t)3 * Bz + b) * Ee + e] * w3;
        cin[(size_t)b * H3 + Hh + e] = v * invL;
    }
    for (int s = tid; s < Ss; s += 256)
        aw_out[b * Ss + s] = __expf(scores[b * Ss + s] - M) * invL;
}

static float* sym(const void* s) {
    void* p = nullptr;
    cudaGetSymbolAddress(&p, s);
    return (float*)p;
}

extern "C" void kernel_launch(void* const* d_in, const int* in_sizes, int n_in,
                              void* d_out, int out_size)
{
    const int*   seq      = (const int*)  d_in[0];
    const float* h0       = (const float*)d_in[1];
    const float* c0       = (const float*)d_in[2];
    const float* enc      = (const float*)d_in[3];
    const float* emb      = (const float*)d_in[4];
    const float* w_ih     = (const float*)d_in[5];
    const float* w_hh     = (const float*)d_in[6];
    const float* b_ih     = (const float*)d_in[7];
    const float* b_hh     = (const float*)d_in[8];
    const float* attn_w   = (const float*)d_in[9];
    const float* concat_w = (const float*)d_in[11];
    const float* concat_b = (const float*)d_in[12];
    const float* out_w    = (const float*)d_in[13];
    const float* out_b    = (const float*)d_in[14];

    float* out    = (float*)d_out;
    float* h_out  = out + (size_t)Bz * Vv;
    float* c_out  = h_out + Bz * Hh;
    float* aw_out = c_out + Bz * Hh;

    float* px     = sym(g_x);
    float* ppart  = sym(g_part);
    float* pgates = sym(g_gates);
    float* pq     = sym(g_q);
    float* psc    = sym(g_scores);
    float* pcin   = sym(g_cin);
    float* pcc    = sym(g_cc);
    float* pctxp  = sym(g_ctxp);
    float* pml    = sym(g_ml);

    cudaFuncSetAttribute(vocab_mma, cudaFuncAttributeMaxDynamicSharedMemorySize,
                         SMEM_ELEMS * 2);
    cudaFuncSetAttribute(mma_gemm<0>, cudaFuncAttributeMaxDynamicSharedMemorySize,
                         G_SMEM_BYTES);
    cudaFuncSetAttribute(mma_gemm<1>, cudaFuncAttributeMaxDynamicSharedMemorySize,
                         G_SMEM_BYTES);

    // 1. embedding
    gather_k<<<(Bz * Hh) / 256, 256>>>(seq, emb, px);

    // 2. LSTM gates (two mma GEMMs, 8 split-K slices total)
    mma_gemm<0><<<dim3(H4 / 128, 4), 256, G_SMEM_BYTES>>>(w_ih, px, ppart, H4, Hh, 8);
    mma_gemm<0><<<dim3(H4 / 128, 4), 256, G_SMEM_BYTES>>>(w_hh, h0,
        ppart + (size_t)4 * 64 * H4, H4, Hh, 8);
    reduce_parts<<<(Bz * H4) / 256, 256>>>(ppart, 8, b_ih, b_hh, pgates, H4, 0);
    lstm_pw<<<(Bz * Hh) / 256, 256>>>(pgates, c0, h_out, c_out, pcin);

    // 3. attention query: q = h_new @ attn_w   (attn_w is [H, E] -> BLAYOUT 1)
    mma_gemm<1><<<dim3(Ee / 128, 4), 256, G_SMEM_BYTES>>>(attn_w, h_out, ppart, Ee, Hh, 8);
    reduce_parts<<<(Bz * Ee) / 256, 256>>>(ppart, 4, nullptr, nullptr, pq, Ee, 0);

    // 4. single-pass attention (split-S flash decoding)
    att_split<<<dim3(4, Bz), 256>>>(pq, enc, psc, pctxp, pml);
    att_combine<<<Bz, 256>>>(pctxp, pml, psc, pcin, aw_out);

    // 5. concat GEMM + tanh
    mma_gemm<0><<<dim3(H3 / 128, 4), 256, G_SMEM_BYTES>>>(concat_w, pcin, ppart, H3, H3, 24);
    reduce_parts<<<(Bz * H3) / 256, 256>>>(ppart, 4, concat_b, nullptr, pcc, H3, 1);

    // 6. vocab GEMM (mma.sync bf16 3-split)
    vocab_mma<<<Vv / MT, 512, SMEM_ELEMS * 2>>>(out_w, pcc, out_b, out);
}

// round 7
// speedup vs baseline: 2.5819x; 1.2636x over previous
#include <cuda_runtime.h>
#include <cuda_bf16.h>
#include <math.h>
#include <cstdint>

// Shapes
#define Bz 64
#define Hh 1024
#define Vv 32000
#define Ss 512
#define Ee 2048   // 2H
#define H3 3072   // 3H
#define H4 4096   // 4H

// ---------------- scratch ----------------
__device__ __align__(16) float g_x[Bz * Hh];
__device__ __align__(16) float g_part[8 * Bz * H4];
__device__ __align__(16) float g_scores[Bz * Ss];
__device__ __align__(16) float g_cin[Bz * H3];
__device__ __align__(16) float g_cc[Bz * H3];
__device__ __align__(16) float g_ctxp[4 * Bz * Ee];
__device__ __align__(16) float g_ml[4 * Bz * 2];

// ================= mma helpers =================
__device__ __forceinline__ void mma16816(float c[4],
    uint32_t a0, uint32_t a1, uint32_t a2, uint32_t a3,
    uint32_t b0, uint32_t b1)
{
    asm volatile(
        "mma.sync.aligned.m16n8k16.row.col.f32.bf16.bf16.f32 "
        "{%0,%1,%2,%3}, {%4,%5,%6,%7}, {%8,%9}, {%0,%1,%2,%3};"
        : "+f"(c[0]), "+f"(c[1]), "+f"(c[2]), "+f"(c[3])
        : "r"(a0), "r"(a1), "r"(a2), "r"(a3), "r"(b0), "r"(b1));
}

__device__ __forceinline__ void cvt4(float4 v, __nv_bfloat16* hi, __nv_bfloat16* lo)
{
    __nv_bfloat16 hx = __float2bfloat16_rn(v.x);
    __nv_bfloat16 hy = __float2bfloat16_rn(v.y);
    __nv_bfloat16 hz = __float2bfloat16_rn(v.z);
    __nv_bfloat16 hw = __float2bfloat16_rn(v.w);
    __nv_bfloat162 h01 = __halves2bfloat162(hx, hy);
    __nv_bfloat162 h23 = __halves2bfloat162(hz, hw);
    *(uint2*)hi = make_uint2(*(uint32_t*)&h01, *(uint32_t*)&h23);
    __nv_bfloat162 l01 = __halves2bfloat162(
        __float2bfloat16_rn(v.x - __bfloat162float(hx)),
        __float2bfloat16_rn(v.y - __bfloat162float(hy)));
    __nv_bfloat162 l23 = __halves2bfloat162(
        __float2bfloat16_rn(v.z - __bfloat162float(hz)),
        __float2bfloat16_rn(v.w - __bfloat162float(hw)));
    *(uint2*)lo = make_uint2(*(uint32_t*)&l01, *(uint32_t*)&l23);
}

// ================= unified 128x64 bf16 3-split GEMM body =================
// C[64, N-tile of 128] over K range. W rows are K-contiguous (BLAYOUT 0) or
// W is [K, N] (BLAYOUT 1, transposed on smem store).
// MODE 0: dst = parts slice base, raw partial write.
// MODE 1: dst = final out [64, N], adds bias.
#define KC 32
#define GSA 40
#define GA_EL (128 * GSA)
#define GB_EL (64 * GSA)
#define G_AHI 0
#define G_ALO (2 * GA_EL)
#define G_BHI (4 * GA_EL)
#define G_BLO (4 * GA_EL + 2 * GB_EL)
#define G_SMEM_BYTES ((4 * GA_EL + 4 * GB_EL) * 2)   // 61440
#define STG_STRIDE 66

template<int BLAYOUT, int MODE>
__device__ __forceinline__ void gemm_body(
    const float* __restrict__ W, const float* __restrict__ act,
    float* __restrict__ dst, const float* __restrict__ bias,
    int N, int K, int kChunks, int n0, int kBase, __nv_bfloat16* gsm)
{
    const int tid  = threadIdx.x;
    const int lane = tid & 31;
    const int w    = tid >> 5;
    const int wm   = w & 3;
    const int wn   = w >> 2;

    float acc[2][4][4];
    #pragma unroll
    for (int i = 0; i < 2; ++i)
        #pragma unroll
        for (int j = 0; j < 4; ++j)
            #pragma unroll
            for (int q = 0; q < 4; ++q) acc[i][j][q] = 0.f;

    float4 pa[4], pbv[2];
    const int ar = tid >> 3;
    const int cg = tid & 7;

    auto loadAB = [&](int k0) {
        if (BLAYOUT == 0) {
            #pragma unroll
            for (int it = 0; it < 4; ++it)
                pa[it] = *(const float4*)&W[(size_t)(n0 + ar + it * 32) * K + k0 + cg * 4];
        } else {
            #pragma unroll
            for (int it = 0; it < 4; ++it)
                pa[it] = *(const float4*)&W[(size_t)(k0 + ar) * N + n0 + (cg + it * 8) * 4];
        }
        pbv[0] = *(const float4*)&act[(size_t)ar * K + k0 + cg * 4];
        pbv[1] = *(const float4*)&act[(size_t)(ar + 32) * K + k0 + cg * 4];
    };
    auto storeAB = [&](int buf) {
        __nv_bfloat16* AH = gsm + G_AHI + buf * GA_EL;
        __nv_bfloat16* AL = gsm + G_ALO + buf * GA_EL;
        if (BLAYOUT == 0) {
            #pragma unroll
            for (int it = 0; it < 4; ++it) {
                int m = ar + it * 32;
                cvt4(pa[it], AH + m * GSA + cg * 4, AL + m * GSA + cg * 4);
            }
        } else {
            #pragma unroll
            for (int it = 0; it < 4; ++it) {
                int ng = cg + it * 8;
                float vv[4] = { pa[it].x, pa[it].y, pa[it].z, pa[it].w };
                #pragma unroll
                for (int f = 0; f < 4; ++f) {
                    int m = ng * 4 + f;
                    __nv_bfloat16 h = __float2bfloat16_rn(vv[f]);
                    AH[m * GSA + ar] = h;
                    AL[m * GSA + ar] = __float2bfloat16_rn(vv[f] - __bfloat162float(h));
                }
            }
        }
        __nv_bfloat16* BH = gsm + G_BHI + buf * GB_EL;
        __nv_bfloat16* BL = gsm + G_BLO + buf * GB_EL;
        cvt4(pbv[0], BH + ar * GSA + cg * 4, BL + ar * GSA + cg * 4);
        cvt4(pbv[1], BH + (ar + 32) * GSA + cg * 4, BL + (ar + 32) * GSA + cg * 4);
    };

    loadAB(kBase);
    storeAB(0);
    __syncthreads();

    const int rg = lane >> 2;
    const int kq = (lane & 3) * 2;

    for (int ch = 0; ch < kChunks; ++ch) {
        const int cur = ch & 1;
        if (ch + 1 < kChunks) loadAB(kBase + (ch + 1) * KC);
        {
            const __nv_bfloat16* Ah = gsm + G_AHI + cur * GA_EL + (wm * 32) * GSA;
            const __nv_bfloat16* Al = gsm + G_ALO + cur * GA_EL + (wm * 32) * GSA;
            const __nv_bfloat16* Bh = gsm + G_BHI + cur * GB_EL + (wn * 32) * GSA;
            const __nv_bfloat16* Bl = gsm + G_BLO + cur * GB_EL + (wn * 32) * GSA;
            #pragma unroll
            for (int ks = 0; ks < KC; ks += 16) {
                const int ko = ks + kq;
                uint32_t ah[2][4], al[2][4], bh[4][2], bl[4][2];
                #pragma unroll
                for (int mt = 0; mt < 2; ++mt) {
                    const __nv_bfloat16* p = Ah + (mt * 16 + rg) * GSA + ko;
                    ah[mt][0] = *(const uint32_t*)p;
                    ah[mt][1] = *(const uint32_t*)(p + 8 * GSA);
                    ah[mt][2] = *(const uint32_t*)(p + 8);
                    ah[mt][3] = *(const uint32_t*)(p + 8 * GSA + 8);
                    const __nv_bfloat16* q = Al + (mt * 16 + rg) * GSA + ko;
                    al[mt][0] = *(const uint32_t*)q;
                    al[mt][1] = *(const uint32_t*)(q + 8 * GSA);
                    al[mt][2] = *(const uint32_t*)(q + 8);
                    al[mt][3] = *(const uint32_t*)(q + 8 * GSA + 8);
                }
                #pragma unroll
                for (int nt = 0; nt < 4; ++nt) {
                    const __nv_bfloat16* p = Bh + (nt * 8 + rg) * GSA + ko;
                    bh[nt][0] = *(const uint32_t*)p;
                    bh[nt][1] = *(const uint32_t*)(p + 8);
                    const __nv_bfloat16* q = Bl + (nt * 8 + rg) * GSA + ko;
                    bl[nt][0] = *(const uint32_t*)q;
                    bl[nt][1] = *(const uint32_t*)(q + 8);
                }
                #pragma unroll
                for (int mt = 0; mt < 2; ++mt)
                    #pragma unroll
                    for (int nt = 0; nt < 4; ++nt) {
                        mma16816(acc[mt][nt], ah[mt][0], ah[mt][1], ah[mt][2], ah[mt][3],
                                 bh[nt][0], bh[nt][1]);
                        mma16816(acc[mt][nt], ah[mt][0], ah[mt][1], ah[mt][2], ah[mt][3],
                                 bl[nt][0], bl[nt][1]);
                        mma16816(acc[mt][nt], al[mt][0], al[mt][1], al[mt][2], al[mt][3],
                                 bh[nt][0], bh[nt][1]);
                    }
            }
        }
        if (ch + 1 < kChunks) storeAB(1 - cur);
        __syncthreads();
    }

    // epilogue via smem stage
    float* stage = (float*)gsm;
    #pragma unroll
    for (int mt = 0; mt < 2; ++mt)
        #pragma unroll
        for (int nt = 0; nt < 4; ++nt) {
            int row = wm * 32 + mt * 16 + rg;
            int col = wn * 32 + nt * 8 + kq;
            *(float2*)&stage[row * STG_STRIDE + col] =
                make_float2(acc[mt][nt][0], acc[mt][nt][1]);
            *(float2*)&stage[(row + 8) * STG_STRIDE + col] =
                make_float2(acc[mt][nt][2], acc[mt][nt][3]);
        }
    __syncthreads();

    {
        const int v  = tid & 127;
        const int b0 = (tid >> 7) * 32;
        float bi = 0.f;
        if (MODE == 1) bi = bias[n0 + v];
        #pragma unroll
        for (int j = 0; j < 32; ++j) {
            int b = b0 + j;
            float val = stage[v * STG_STRIDE + b];
            if (MODE == 1)
                dst[(size_t)b * N + n0 + v] = val + bi;
            else
                dst[(size_t)b * N + n0 + v] = val;
        }
    }
}

template<int BLAYOUT>
__global__ void __launch_bounds__(256, 2) k_gemm_part(
    const float* __restrict__ W, const float* __restrict__ act,
    float* __restrict__ parts, int N, int K, int kChunks)
{
    extern __shared__ __align__(16) __nv_bfloat16 gsm[];
    gemm_body<BLAYOUT, 0>(W, act, parts + (size_t)blockIdx.y * 64 * N, nullptr,
                          N, K, kChunks, blockIdx.x * 128,
                          blockIdx.y * kChunks * KC, gsm);
}

__global__ void __launch_bounds__(256, 2) k_gemm_dual(
    const float* __restrict__ W0, const float* __restrict__ W1,
    const float* __restrict__ a0, const float* __restrict__ a1,
    float* __restrict__ parts, int N, int K, int kChunks)
{
    extern __shared__ __align__(16) __nv_bfloat16 gsm[];
    const float* W = blockIdx.z ? W1 : W0;
    const float* A = blockIdx.z ? a1 : a0;
    int slice = blockIdx.y + 4 * blockIdx.z;
    gemm_body<0, 0>(W, A, parts + (size_t)slice * 64 * N, nullptr,
                    N, K, kChunks, blockIdx.x * 128,
                    blockIdx.y * kChunks * KC, gsm);
}

__global__ void __launch_bounds__(256, 2) k_gemm_direct(
    const float* __restrict__ W, const float* __restrict__ act,
    float* __restrict__ out, const float* __restrict__ bias,
    int N, int K, int kChunks)
{
    extern __shared__ __align__(16) __nv_bfloat16 gsm[];
    gemm_body<0, 1>(W, act, out, bias, N, K, kChunks, blockIdx.x * 128, 0, gsm);
}

// ================= split-K reduce for concat (+bias +tanh) =================
template<int NSL>
__global__ void reduceN(const float* __restrict__ parts,
                        const float* __restrict__ b1,
                        float* __restrict__ C, int N)
{
    int i4 = blockIdx.x * 256 + threadIdx.x;
    const float4* p4 = (const float4*)parts;
    float4 s = p4[i4];
    #pragma unroll
    for (int sl = 1; sl < NSL; ++sl) {
        float4 v = p4[(size_t)sl * (64 * N / 4) + i4];
        s.x += v.x; s.y += v.y; s.z += v.z; s.w += v.w;
    }
    int n4 = i4 % (N / 4);
    float4 bv = ((const float4*)b1)[n4];
    s.x = tanhf(s.x + bv.x);
    s.y = tanhf(s.y + bv.y);
    s.z = tanhf(s.z + bv.z);
    s.w = tanhf(s.w + bv.w);
    ((float4*)C)[i4] = s;
}

// ================= pointwise =================
__global__ void gather_k(const int* __restrict__ seq, const float* __restrict__ emb,
                         float* __restrict__ x)
{
    int idx = blockIdx.x * 256 + threadIdx.x;
    int b = idx >> 10;
    x[idx] = emb[(size_t)seq[b] * Hh + (idx & 1023)];
}

__device__ __forceinline__ float sigf(float x) { return 1.f / (1.f + expf(-x)); }

// LSTM pointwise, reading 8 split-K partial slices directly (N = H4)
__global__ void lstm_pw2(const float* __restrict__ parts,
                         const float* __restrict__ b_ih, const float* __restrict__ b_hh,
                         const float* __restrict__ c0,
                         float* __restrict__ h_out, float* __restrict__ c_out,
                         float* __restrict__ cin)
{
    int idx = blockIdx.x * 256 + threadIdx.x;   // 64*1024
    int b = idx >> 10, h = idx & 1023;
    float gate[4];
    #pragma unroll
    for (int g = 0; g < 4; ++g) {
        int n = g * Hh + h;
        float s = b_ih[n] + b_hh[n];
        #pragma unroll
        for (int sl = 0; sl < 8; ++sl)
            s += parts[(size_t)sl * 64 * H4 + (size_t)b * H4 + n];
        gate[g] = s;
    }
    float ig = sigf(gate[0]);
    float fg = sigf(gate[1]);
    float gg = tanhf(gate[2]);
    float og = sigf(gate[3]);
    float c = fg * c0[idx] + ig * gg;
    float hn = og * tanhf(c);
    c_out[idx] = c;
    h_out[idx] = hn;
    cin[(size_t)b * H3 + h] = hn;
}

// ================= single-pass split-S attention (4-s batched) =================
__global__ void __launch_bounds__(256) att_split(
    const float* __restrict__ qparts, const float* __restrict__ enc,
    float* __restrict__ scores, float* __restrict__ ctxp, float* __restrict__ ml)
{
    __shared__ float wsum[2][8][4];
    const int b = blockIdx.y, sp = blockIdx.x;
    const int tid = threadIdx.x, lane = tid & 31, w = tid >> 5;
    const int e0 = tid * 4;

    // q = sum of 8 split-K partial slices (N = Ee)
    float4 q0 = make_float4(0.f, 0.f, 0.f, 0.f);
    float4 q1 = make_float4(0.f, 0.f, 0.f, 0.f);
    #pragma unroll
    for (int sl = 0; sl < 8; ++sl) {
        const float* qp = qparts + (size_t)sl * 64 * Ee + (size_t)b * Ee;
        float4 a = *(const float4*)&qp[e0];
        float4 c = *(const float4*)&qp[1024 + e0];
        q0.x += a.x; q0.y += a.y; q0.z += a.z; q0.w += a.w;
        q1.x += c.x; q1.y += c.y; q1.z += c.z; q1.w += c.w;
    }

    float m = -INFINITY, l = 0.f;
    float4 c0 = make_float4(0.f, 0.f, 0.f, 0.f);
    float4 c1 = make_float4(0.f, 0.f, 0.f, 0.f);

    const int sBeg = sp * 128;
    const float* base = enc + (size_t)b * Ee + e0;

    float4 ce[4][2];
    #pragma unroll
    for (int j = 0; j < 4; ++j) {
        ce[j][0] = *(const float4*)&base[(size_t)(sBeg + j) * (Bz * Ee)];
        ce[j][1] = *(const float4*)&base[(size_t)(sBeg + j) * (Bz * Ee) + 1024];
    }

    for (int g = 0; g < 32; ++g) {
        const int s0 = sBeg + g * 4;
        const int buf = g & 1;

        float d[4];
        #pragma unroll
        for (int j = 0; j < 4; ++j)
            d[j] = q0.x * ce[j][0].x + q0.y * ce[j][0].y + q0.z * ce[j][0].z + q0.w * ce[j][0].w
                 + q1.x * ce[j][1].x + q1.y * ce[j][1].y + q1.z * ce[j][1].z + q1.w * ce[j][1].w;

        float4 ne[4][2];
        if (g < 31) {
            #pragma unroll
            for (int j = 0; j < 4; ++j) {
                ne[j][0] = *(const float4*)&base[(size_t)(s0 + 4 + j) * (Bz * Ee)];
                ne[j][1] = *(const float4*)&base[(size_t)(s0 + 4 + j) * (Bz * Ee) + 1024];
            }
        }

        #pragma unroll
        for (int o = 16; o; o >>= 1)
            #pragma unroll
            for (int j = 0; j < 4; ++j)
                d[j] += __shfl_xor_sync(0xffffffffu, d[j], o);
        if (lane < 4) wsum[buf][w][lane] = d[lane];
        __syncthreads();

        float sc[4];
        #pragma unroll
        for (int j = 0; j < 4; ++j) {
            float s = 0.f;
            #pragma unroll
            for (int ww = 0; ww < 8; ++ww) s += wsum[buf][ww][j];
            sc[j] = s;
        }
        if (tid < 4) scores[b * Ss + s0 + tid] = sc[tid];

        float mloc = fmaxf(fmaxf(sc[0], sc[1]), fmaxf(sc[2], sc[3]));
        float mn = fmaxf(m, mloc);
        float scale = __expf(m - mn);
        float pw[4];
        float psum = 0.f;
        #pragma unroll
        for (int j = 0; j < 4; ++j) { pw[j] = __expf(sc[j] - mn); psum += pw[j]; }
        l = l * scale + psum;
        c0.x = c0.x * scale; c0.y = c0.y * scale; c0.z = c0.z * scale; c0.w = c0.w * scale;
        c1.x = c1.x * scale; c1.y = c1.y * scale; c1.z = c1.z * scale; c1.w = c1.w * scale;
        #pragma unroll
        for (int j = 0; j < 4; ++j) {
            c0.x += pw[j] * ce[j][0].x; c0.y += pw[j] * ce[j][0].y;
            c0.z += pw[j] * ce[j][0].z; c0.w += pw[j] * ce[j][0].w;
            c1.x += pw[j] * ce[j][1].x; c1.y += pw[j] * ce[j][1].y;
            c1.z += pw[j] * ce[j][1].z; c1.w += pw[j] * ce[j][1].w;
        }
        m = mn;
        #pragma unroll
        for (int j = 0; j < 4; ++j) { ce[j][0] = ne[j][0]; ce[j][1] = ne[j][1]; }
    }

    float* cp = ctxp + ((size_t)sp * Bz + b) * Ee;
    *(float4*)&cp[e0] = c0;
    *(float4*)&cp[1024 + e0] = c1;
    if (tid == 0) {
        ml[(sp * Bz + b) * 2 + 0] = m;
        ml[(sp * Bz + b) * 2 + 1] = l;
    }
}

__global__ void __launch_bounds__(256) att_combine(
    const float* __restrict__ ctxp, const float* __restrict__ ml,
    const float* __restrict__ scores, float* __restrict__ cin,
    float* __restrict__ aw_out)
{
    const int b = blockIdx.x, tid = threadIdx.x;
    float m0 = ml[(0 * Bz + b) * 2], l0 = ml[(0 * Bz + b) * 2 + 1];
    float m1 = ml[(1 * Bz + b) * 2], l1 = ml[(1 * Bz + b) * 2 + 1];
    float m2 = ml[(2 * Bz + b) * 2], l2 = ml[(2 * Bz + b) * 2 + 1];
    float m3 = ml[(3 * Bz + b) * 2], l3 = ml[(3 * Bz + b) * 2 + 1];
    float M = fmaxf(fmaxf(m0, m1), fmaxf(m2, m3));
    float w0 = __expf(m0 - M), w1 = __expf(m1 - M);
    float w2 = __expf(m2 - M), w3 = __expf(m3 - M);
    float L = l0 * w0 + l1 * w1 + l2 * w2 + l3 * w3;
    float invL = 1.f / L;

    for (int e = tid; e < Ee; e += 256) {
        float v = ctxp[((size_t)0 * Bz + b) * Ee + e] * w0
                + ctxp[((size_t)1 * Bz + b) * Ee + e] * w1
                + ctxp[((size_t)2 * Bz + b) * Ee + e] * w2
                + ctxp[((size_t)3 * Bz + b) * Ee + e] * w3;
        cin[(size_t)b * H3 + Hh + e] = v * invL;
    }
    for (int s = tid; s < Ss; s += 256)
        aw_out[b * Ss + s] = __expf(scores[b * Ss + s] - M) * invL;
}

static float* sym(const void* s) {
    void* p = nullptr;
    cudaGetSymbolAddress(&p, s);
    return (float*)p;
}

extern "C" void kernel_launch(void* const* d_in, const int* in_sizes, int n_in,
                              void* d_out, int out_size)
{
    const int*   seq      = (const int*)  d_in[0];
    const float* h0       = (const float*)d_in[1];
    const float* c0       = (const float*)d_in[2];
    const float* enc      = (const float*)d_in[3];
    const float* emb      = (const float*)d_in[4];
    const float* w_ih     = (const float*)d_in[5];
    const float* w_hh     = (const float*)d_in[6];
    const float* b_ih     = (const float*)d_in[7];
    const float* b_hh     = (const float*)d_in[8];
    const float* attn_w   = (const float*)d_in[9];
    const float* concat_w = (const float*)d_in[11];
    const float* concat_b = (const float*)d_in[12];
    const float* out_w    = (const float*)d_in[13];
    const float* out_b    = (const float*)d_in[14];

    float* out    = (float*)d_out;
    float* h_out  = out + (size_t)Bz * Vv;
    float* c_out  = h_out + Bz * Hh;
    float* aw_out = c_out + Bz * Hh;

    float* px     = sym(g_x);
    float* ppart  = sym(g_part);
    float* psc    = sym(g_scores);
    float* pcin   = sym(g_cin);
    float* pcc    = sym(g_cc);
    float* pctxp  = sym(g_ctxp);
    float* pml    = sym(g_ml);

    cudaFuncSetAttribute(k_gemm_part<0>, cudaFuncAttributeMaxDynamicSharedMemorySize, G_SMEM_BYTES);
    cudaFuncSetAttribute(k_gemm_part<1>, cudaFuncAttributeMaxDynamicSharedMemorySize, G_SMEM_BYTES);
    cudaFuncSetAttribute(k_gemm_dual,    cudaFuncAttributeMaxDynamicSharedMemorySize, G_SMEM_BYTES);
    cudaFuncSetAttribute(k_gemm_direct,  cudaFuncAttributeMaxDynamicSharedMemorySize, G_SMEM_BYTES);

    // 1. embedding
    gather_k<<<(Bz * Hh) / 256, 256>>>(seq, emb, px);

    // 2. LSTM gates: both GEMMs in one launch (z: 0 = w_ih@x, 1 = w_hh@h0)
    k_gemm_dual<<<dim3(H4 / 128, 4, 2), 256, G_SMEM_BYTES>>>(
        w_ih, w_hh, px, h0, ppart, H4, Hh, 8);
    lstm_pw2<<<(Bz * Hh) / 256, 256>>>(ppart, b_ih, b_hh, c0, h_out, c_out, pcin);

    // 3. attention query: q = h_new @ attn_w (attn_w is [H, E]); 8 split-K slices,
    //    summed inside att_split
    k_gemm_part<1><<<dim3(Ee / 128, 8), 256, G_SMEM_BYTES>>>(attn_w, h_out, ppart, Ee, Hh, 4);

    // 4. single-pass attention
    att_split<<<dim3(4, Bz), 256>>>(ppart, enc, psc, pctxp, pml);
    att_combine<<<Bz, 256>>>(pctxp, pml, psc, pcin, aw_out);

    // 5. concat GEMM + tanh (6 split-K slices)
    k_gemm_part<0><<<dim3(H3 / 128, 6), 256, G_SMEM_BYTES>>>(concat_w, pcin, ppart, H3, H3, 16);
    reduceN<6><<<(Bz * H3 / 4) / 256, 256>>>(ppart, concat_b, pcc, H3);

    // 6. vocab GEMM: direct write + bias, 250 CTAs, 2 CTAs/SM
    k_gemm_direct<<<Vv / 128, 256, G_SMEM_BYTES>>>(out_w, pcc, out, out_b, Vv, H3, 96);
}